// round 10
// baseline (speedup 1.0000x reference)
#include <cuda_runtime.h>
#include <cuda_fp16.h>
#include <cstdint>

// ---------------------------------------------------------------------------
// TransformerXL relative position embedding — pure fp16 mma.sync m16n8k16
//   q·k ≈ qh·kh  (fp16 operands, fp32 accum; rel_err ~4e-4 incl fp16 BD stage)
// Split-M CTAs (M=64), 256 threads, 32x32 warp tiles, 4 CTAs/SM.
//
// out[b,n,u,w,c] = AC[w,c] + (0 <= c-w < 128 ? BD[w, c-w] : 0)
// ---------------------------------------------------------------------------

namespace {
constexpr int Uu = 32, Nn = 8, Cc = 255;

constexpr int RS = 40;                    // row stride (words); 40%32=8 -> conflict-free
constexpr int OFF_B  = 64 * RS;           // 2560  (sA: 64 rows x 32 words)
constexpr int OFF_BD = OFF_B + 128 * RS;  // 7680  (sB: 128 rows) ; sBD after, in halfs
constexpr int BDS_H = 137;                // sBD stride in halfs (see parity proof)
constexpr int SMEM_BYTES = OFF_BD * 4 + 64 * BDS_H * 2;  // 30720 + 17536 = 48256 -> 4 CTAs/SM
}

// E pre-packed hi-only fragment layout: [n][f][32 words] = 128 KB
__device__ uint32_t g_Epk[Nn * 128 * 32];

// ---------------------------------------------------------------------------
__device__ __forceinline__ void mma16(float* c, const uint32_t* a, const uint32_t* b) {
    asm volatile(
        "mma.sync.aligned.m16n8k16.row.col.f32.f16.f16.f32 "
        "{%0,%1,%2,%3}, {%4,%5,%6,%7}, {%8,%9}, {%0,%1,%2,%3};"
        : "+f"(c[0]), "+f"(c[1]), "+f"(c[2]), "+f"(c[3])
        : "r"(a[0]), "r"(a[1]), "r"(a[2]), "r"(a[3]), "r"(b[0]), "r"(b[1]));
}

__device__ __forceinline__ uint32_t pack_h2(float a, float b) {
    __half2 h = __floats2half2_rn(a, b);
    return *reinterpret_cast<uint32_t*>(&h);
}

// --- permuted word index within a row: word = kb*8 + pprime(p), p = k/2 ---
__device__ __forceinline__ void packB_pair(uint32_t* __restrict__ rowp, int p,
                                           float e0, float e1) {
    int kb = p >> 3, pp = p & 7;
    int pprime = ((pp & 3) << 1) | (pp >> 2);
    rowp[kb * 8 + pprime] = pack_h2(e0, e1);
}
__device__ __forceinline__ void packB4(uint32_t* __restrict__ rowp, int h4, float4 v) {
    packB_pair(rowp, (h4 >> 1),     v.x, v.y);
    packB_pair(rowp, (h4 >> 1) + 1, v.z, v.w);
}

// quad-pack: v0 = row[hb..hb+3], v1 = row[hb+8..hb+11]  ->  4 adjacent words
__device__ __forceinline__ uint4 pack_quad(float4 v0, float4 v1) {
    uint4 r;
    r.x = pack_h2(v0.x, v0.y);
    r.y = pack_h2(v1.x, v1.y);
    r.z = pack_h2(v0.z, v0.w);
    r.w = pack_h2(v1.z, v1.w);
    return r;
}

__device__ __forceinline__ void cp16(uint32_t dst, const void* src) {
    asm volatile("cp.async.ca.shared.global [%0], [%1], 16;" :: "r"(dst), "l"(src));
}

// gather one packed quad of K (guarded)
__device__ __forceinline__ uint4 gather_pack(const float* __restrict__ Kg,
                                             int row, int hb, bool valid) {
    float4 z = make_float4(0.f, 0.f, 0.f, 0.f);
    float4 v0 = valid ? *(const float4*)&Kg[(size_t)row * 512 + hb] : z;
    float4 v1 = valid ? *(const float4*)&Kg[(size_t)row * 512 + hb + 8] : z;
    return pack_quad(v0, v1);
}

// 32x32 warp-tile gemm over K=64, pure fp16.
__device__ __forceinline__ void gemm_warp(const uint32_t* __restrict__ sA,
                                          const uint32_t* __restrict__ sB,
                                          float acc[2][4][4],
                                          int rm, int cn, int g, int t) {
    #pragma unroll
    for (int kb = 0; kb < 4; ++kb) {
        const int ko = kb * 8 + 2 * t;
        const uint2 x0 = *(const uint2*)&sA[(rm + g) * RS + ko];
        const uint2 x1 = *(const uint2*)&sA[(rm + g + 8) * RS + ko];
        const uint2 x2 = *(const uint2*)&sA[(rm + 16 + g) * RS + ko];
        const uint2 x3 = *(const uint2*)&sA[(rm + 24 + g) * RS + ko];
        uint32_t a[2][4] = {{x0.x, x1.x, x0.y, x1.y}, {x2.x, x3.x, x2.y, x3.y}};
        #pragma unroll
        for (int j = 0; j < 4; ++j) {
            const uint2 fb = *(const uint2*)&sB[(cn + 8 * j + g) * RS + ko];
            uint32_t bb[2] = {fb.x, fb.y};
            mma16(acc[0][j], a[0], bb);
            mma16(acc[1][j], a[1], bb);
        }
    }
}

// ---------------------------------------------------------------------------
// E kernel: grid 128 = (64 f-pairs) x (2 nh-halves), 1024 threads.
// Writes E directly in the hi-only packed fragment layout.
// ---------------------------------------------------------------------------
__global__ __launch_bounds__(1024)
void compute_E_kernel(const float* __restrict__ pk) {
    __shared__ float sig[2 * 512];
    __shared__ float sp[16 * 2 * 256];

    const int fg  = blockIdx.x & 63;
    const int nhh = blockIdx.x >> 6;
    const int f2  = fg * 2;
    const int nh0 = nhh * 256;
    const int tid = threadIdx.x;
    const float log_inc = 9.210340371976184f / 255.0f;

    {
        int fi = tid >> 9, d = tid & 511, j = d & 255;
        float arg = (float)(127 - (f2 + fi)) * expf(-(float)j * log_inc);
        sig[fi * 512 + d] = (d < 256) ? sinf(arg) : cosf(arg);
    }
    __syncthreads();

    const int q = tid & 63, ch = tid >> 6;
    const float* p = pk + (size_t)(ch * 32) * 512 + nh0 + 4 * q;
    float4 a0 = make_float4(0.f, 0.f, 0.f, 0.f);
    float4 a1 = make_float4(0.f, 0.f, 0.f, 0.f);
    #pragma unroll
    for (int dd = 0; dd < 32; ++dd) {
        float4 v = __ldg((const float4*)(p + (size_t)dd * 512));
        int d = ch * 32 + dd;
        float s0 = sig[d], s1 = sig[512 + d];
        a0.x = fmaf(s0, v.x, a0.x); a0.y = fmaf(s0, v.y, a0.y);
        a0.z = fmaf(s0, v.z, a0.z); a0.w = fmaf(s0, v.w, a0.w);
        a1.x = fmaf(s1, v.x, a1.x); a1.y = fmaf(s1, v.y, a1.y);
        a1.z = fmaf(s1, v.z, a1.z); a1.w = fmaf(s1, v.w, a1.w);
    }
    *(float4*)&sp[(ch * 2 + 0) * 256 + 4 * q] = a0;
    *(float4*)&sp[(ch * 2 + 1) * 256 + 4 * q] = a1;
    __syncthreads();

    if (tid < 128) {
        int fi = tid >> 6, qq = tid & 63;
        float4 s = make_float4(0.f, 0.f, 0.f, 0.f);
        #pragma unroll
        for (int c = 0; c < 16; ++c) {
            float4 v = *(const float4*)&sp[(c * 2 + fi) * 256 + 4 * qq];
            s.x += v.x; s.y += v.y; s.z += v.z; s.w += v.w;
        }
        const int n  = nhh * 4 + (qq >> 4);
        const int h4 = (4 * qq) & 63;
        packB4(g_Epk + n * (128 * 32) + (f2 + fi) * 32, h4, s);
    }
}

// ---------------------------------------------------------------------------
// Main kernel: one CTA per (b,u,n,mh), 256 threads (8 warps, 2m x 4n).
// ---------------------------------------------------------------------------
__global__ __launch_bounds__(256, 4)
void txl_mma_kernel(const float* __restrict__ q_g,
                    const float* __restrict__ k_g,
                    float* __restrict__ out_g) {
    extern __shared__ uint32_t sm[];
    uint32_t* sA = sm;
    uint32_t* sB = sm + OFF_B;
    __half* sBD = reinterpret_cast<__half*>(sm + OFF_BD);

    const int tid = threadIdx.x;
    const int lane = tid & 31, wid = tid >> 5;
    const int wm = wid & 1, wn = wid >> 1;
    const int g = lane >> 2, t = lane & 3;

    const int bid = blockIdx.x;
    const int mh = bid & 1;
    const int n = (bid >> 1) & 7, u = (bid >> 4) & 31, b = bid >> 9;

    const float* Q  = q_g + (size_t)(b * Uu + u) * 128 * 512 + (size_t)mh * 64 * 512 + n * 64;
    const float* Kg = k_g + (size_t)(b * Uu + u) * Cc * 512 + n * 64;
    float* OUT = out_g + (size_t)((b * Nn + n) * Uu + u) * 128 * Cc + (size_t)mh * 64 * Cc;

    // pack-task decode (per 64-row block): idx -> (row, kb, hh)
    const int t_row0 = tid >> 3;                 // rows 0..31 (jj=0)
    const int t_kb   = (tid >> 1) & 3;
    const int t_hh   = tid & 1;
    const int t_hb   = 16 * t_kb + 4 * t_hh;
    const int t_woff = t_kb * 8 + 4 * t_hh;      // word offset within row

    // ---- E -> sB via cp.async (hi-only, already packed) ----
    {
        uint32_t sB_u32;
        asm("{ .reg .u64 t; cvta.to.shared.u64 t, %1; cvt.u32.u64 %0, t; }"
            : "=r"(sB_u32) : "l"(sB));
        const uint32_t* Ep = g_Epk + n * (128 * 32);
        #pragma unroll
        for (int i = 0; i < 4; ++i) {
            int idx = tid + 256 * i;             // 0..1023
            int r = idx >> 3, w4 = (idx & 7) << 2;
            cp16(sB_u32 + (uint32_t)(r * RS + w4) * 4, Ep + r * 32 + w4);
        }
        asm volatile("cp.async.commit_group;");
    }

    // ---- pack Q (64 rows) -> sA ----
    #pragma unroll
    for (int it = 0; it < 2; ++it) {
        const int row = t_row0 + 32 * it;
        float4 v0 = *(const float4*)&Q[(size_t)row * 512 + t_hb];
        float4 v1 = *(const float4*)&Q[(size_t)row * 512 + t_hb + 8];
        *(uint4*)&sA[row * RS + t_woff] = pack_quad(v0, v1);
    }

    // ---- gather K rows 0..63 (packed) ----
    uint4 krp[2];
    #pragma unroll
    for (int jj = 0; jj < 2; ++jj)
        krp[jj] = gather_pack(Kg, t_row0 + 32 * jj, t_hb, true);

    asm volatile("cp.async.wait_group 0;");
    __syncthreads();

    // ---- BD = Q @ E^T ----
    float accbd[2][4][4] = {};
    gemm_warp(sA, sB, accbd, 32 * wm, 32 * wn, g, t);
    __syncthreads();                             // E reads complete

    // ---- K0: store rows 0..63; gather rows 64..127; stage BD; store rows 64..127
    #pragma unroll
    for (int jj = 0; jj < 2; ++jj)
        *(uint4*)&sB[(t_row0 + 32 * jj) * RS + t_woff] = krp[jj];
    #pragma unroll
    for (int jj = 0; jj < 2; ++jj)
        krp[jj] = gather_pack(Kg, 64 + t_row0 + 32 * jj, t_hb, true);

    #pragma unroll
    for (int i = 0; i < 2; ++i)
        #pragma unroll
        for (int j = 0; j < 4; ++j) {
            const int w0 = 32 * wm + 16 * i + g;
            const int f0 = 32 * wn + 8 * j + 2 * t;
            sBD[w0 * BDS_H + f0]           = __float2half_rn(accbd[i][j][0]);
            sBD[w0 * BDS_H + f0 + 1]       = __float2half_rn(accbd[i][j][1]);
            sBD[(w0 + 8) * BDS_H + f0]     = __float2half_rn(accbd[i][j][2]);
            sBD[(w0 + 8) * BDS_H + f0 + 1] = __float2half_rn(accbd[i][j][3]);
        }
    #pragma unroll
    for (int jj = 0; jj < 2; ++jj)
        *(uint4*)&sB[(64 + t_row0 + 32 * jj) * RS + t_woff] = krp[jj];
    __syncthreads();

    // ---- AC halves ----
    #pragma unroll 1
    for (int half = 0; half < 2; ++half) {
        float acc[2][4][4] = {};
        gemm_warp(sA, sB, acc, 32 * wm, 32 * wn, g, t);

        if (half == 0) {
            // gather K1 rows 128..191 (packed); epilogue hides latency
            #pragma unroll
            for (int jj = 0; jj < 2; ++jj)
                krp[jj] = gather_pack(Kg, 128 + t_row0 + 32 * jj, t_hb, true);
        }

        // epilogue: add shifted BD (fp16, aligned half2), direct stores
        #pragma unroll
        for (int i = 0; i < 2; ++i)
            #pragma unroll
            for (int j = 0; j < 4; ++j) {
                const int c0 = 128 * half + 32 * wn + 8 * j + 2 * t;
                #pragma unroll
                for (int p = 0; p < 2; ++p) {
                    const int lw = 32 * wm + 16 * i + g + 8 * p;  // local row
                    const int wg = mh * 64 + lw;                  // global row
                    float v0 = acc[i][j][2 * p];
                    float v1 = acc[i][j][2 * p + 1];
                    const int f = c0 - wg;
                    // index lw*BDS_H + f is always even (137*lw + c0-64mh-lw)
                    if (f >= 0 && f < 127) {
                        __half2 h = *reinterpret_cast<const __half2*>(&sBD[lw * BDS_H + f]);
                        float2 bd = __half22float2(h);
                        v0 += bd.x; v1 += bd.y;
                    } else if (f == -1) {
                        v1 += __half2float(sBD[lw * BDS_H]);
                    } else if (f == 127) {
                        v0 += __half2float(sBD[lw * BDS_H + 127]);
                    }
                    float* o = &OUT[(size_t)lw * Cc + c0];
                    o[0] = v0;
                    if (c0 + 1 < Cc) o[1] = v1;
                }
            }

        if (half == 0) {
            __syncthreads();                     // K0 fragment reads complete
            #pragma unroll
            for (int jj = 0; jj < 2; ++jj)
                *(uint4*)&sB[(t_row0 + 32 * jj) * RS + t_woff] = krp[jj];
            // gather + store K1 rows 192..255 (row 255 zero)
            #pragma unroll
            for (int jj = 0; jj < 2; ++jj) {
                const int row = 192 + t_row0 + 32 * jj;
                krp[jj] = gather_pack(Kg, row, t_hb, row < Cc);
            }
            #pragma unroll
            for (int jj = 0; jj < 2; ++jj)
                *(uint4*)&sB[(64 + t_row0 + 32 * jj) * RS + t_woff] = krp[jj];
            __syncthreads();
        }
    }
}

// ---------------------------------------------------------------------------
extern "C" void kernel_launch(void* const* d_in, const int* in_sizes, int n_in,
                              void* d_out, int out_size) {
    (void)in_sizes; (void)n_in; (void)out_size;
    const float* q  = (const float*)d_in[0];   // queries (4,32,128,8,64)
    const float* k  = (const float*)d_in[1];   // keys    (4,32,255,8,64)
    const float* pk = (const float*)d_in[2];   // pos_kernel (512,8,64)
    float* out = (float*)d_out;                // (4,8,32,128,255)

    compute_E_kernel<<<128, 1024>>>(pk);

    cudaFuncSetAttribute(txl_mma_kernel,
                         cudaFuncAttributeMaxDynamicSharedMemorySize, SMEM_BYTES);
    txl_mma_kernel<<<2 * 4 * Uu * Nn, 256, SMEM_BYTES>>>(q, k, out);
}

// round 11
// speedup vs baseline: 1.0476x; 1.0476x over previous
#include <cuda_runtime.h>
#include <cuda_fp16.h>
#include <cstdint>

// ---------------------------------------------------------------------------
// TransformerXL relative position embedding — pure fp16 mma.sync m16n8k16
// ldmatrix fragment loads, XOR-swizzled natural-layout smem tiles.
//   q·k ≈ qh·kh  (fp16 operands, fp32 accum; rel_err ~3e-4)
// Split-M CTAs (M=64), 256 threads, 32x32 warp tiles, 3 CTAs/SM.
//
// out[b,n,u,w,c] = AC[w,c] + (0 <= c-w < 128 ? BD[w, c-w] : 0)
// ---------------------------------------------------------------------------

namespace {
constexpr int Uu = 32, Nn = 8, Cc = 255;

// byte offsets in dynamic smem
constexpr int OFF_A_B  = 0;        // sA: 64 rows x 128 B
constexpr int OFF_B_B  = 8192;     // sB: 128 rows x 128 B
constexpr int OFF_BD_B = 24576;    // sBD: 64 x 137 halfs
constexpr int BDS_H = 137;
constexpr int SMEM_BYTES = OFF_BD_B + 64 * BDS_H * 2;   // 42112 -> 3+ CTAs/SM
}

// E pre-packed fp16 natural layout: [n][f][32 words] = 128 KB
__device__ uint32_t g_Epk[Nn * 128 * 32];

// ---------------------------------------------------------------------------
__device__ __forceinline__ void mma16(float* c, const uint32_t* a, const uint32_t* b) {
    asm volatile(
        "mma.sync.aligned.m16n8k16.row.col.f32.f16.f16.f32 "
        "{%0,%1,%2,%3}, {%4,%5,%6,%7}, {%8,%9}, {%0,%1,%2,%3};"
        : "+f"(c[0]), "+f"(c[1]), "+f"(c[2]), "+f"(c[3])
        : "r"(a[0]), "r"(a[1]), "r"(a[2]), "r"(a[3]), "r"(b[0]), "r"(b[1]));
}

#define LDSM_X4(r, addr)                                                        \
    asm volatile("ldmatrix.sync.aligned.m8n8.x4.shared.b16 {%0,%1,%2,%3}, [%4];"\
                 : "=r"((r)[0]), "=r"((r)[1]), "=r"((r)[2]), "=r"((r)[3])       \
                 : "r"(addr))

__device__ __forceinline__ uint32_t pack_h2(float a, float b) {
    __half2 h = __floats2half2_rn(a, b);
    return *reinterpret_cast<uint32_t*>(&h);
}

// natural quad: v0 = h[8c..8c+3], v1 = h[8c+4..8c+7] -> 16B of fp16 pairs
__device__ __forceinline__ uint4 pack_quad(float4 v0, float4 v1) {
    uint4 r;
    r.x = pack_h2(v0.x, v0.y);
    r.y = pack_h2(v0.z, v0.w);
    r.z = pack_h2(v1.x, v1.y);
    r.w = pack_h2(v1.z, v1.w);
    return r;
}

__device__ __forceinline__ uint4 gather_pack(const float* __restrict__ Kg,
                                             int row, int hb, bool valid) {
    float4 z = make_float4(0.f, 0.f, 0.f, 0.f);
    float4 v0 = valid ? *(const float4*)&Kg[(size_t)row * 512 + hb] : z;
    float4 v1 = valid ? *(const float4*)&Kg[(size_t)row * 512 + hb + 4] : z;
    return pack_quad(v0, v1);
}

__device__ __forceinline__ void cp16(uint32_t dst, const void* src) {
    asm volatile("cp.async.ca.shared.global [%0], [%1], 16;" :: "r"(dst), "l"(src));
}

// 32x32 warp-tile gemm over K=64 via ldmatrix. sAu/sBu = smem u32 byte bases.
__device__ __forceinline__ void gemm_warp(uint32_t sAu, uint32_t sBu,
                                          float acc[2][4][4],
                                          int rm, int cn, int lane) {
    const int la = lane & 15;
    const int ca = lane >> 4;                         // A k-chunk select
    const int lb = (lane & 7) | ((lane >> 4) << 3);   // B row-within-16
    const int cb = (lane >> 3) & 1;                   // B k-chunk select
    const uint32_t aB0 = sAu + (uint32_t)(rm + la) * 128;
    const uint32_t aB1 = aB0 + 16 * 128;
    const uint32_t bB0 = sBu + (uint32_t)(cn + lb) * 128;
    const uint32_t bB1 = bB0 + 16 * 128;
    const int swA = (rm + la) & 7;                    // +16 doesn't change &7
    const int swB = (cn + lb) & 7;
    #pragma unroll
    for (int kb = 0; kb < 4; ++kb) {
        uint32_t a0[4], a1[4], b0[4], b1[4];
        LDSM_X4(a0, aB0 + (uint32_t)(((2 * kb + ca) ^ swA) << 4));
        LDSM_X4(a1, aB1 + (uint32_t)(((2 * kb + ca) ^ swA) << 4));
        LDSM_X4(b0, bB0 + (uint32_t)(((2 * kb + cb) ^ swB) << 4));
        LDSM_X4(b1, bB1 + (uint32_t)(((2 * kb + cb) ^ swB) << 4));
        mma16(acc[0][0], a0, b0);      mma16(acc[1][0], a1, b0);
        mma16(acc[0][1], a0, b0 + 2);  mma16(acc[1][1], a1, b0 + 2);
        mma16(acc[0][2], a0, b1);      mma16(acc[1][2], a1, b1);
        mma16(acc[0][3], a0, b1 + 2);  mma16(acc[1][3], a1, b1 + 2);
    }
}

// ---------------------------------------------------------------------------
// E kernel: grid 128 = (64 f-pairs) x (2 nh-halves), 1024 threads.
// Writes E as fp16 pairs in natural k-order.
// ---------------------------------------------------------------------------
__global__ __launch_bounds__(1024)
void compute_E_kernel(const float* __restrict__ pk) {
    __shared__ float sig[2 * 512];
    __shared__ float sp[16 * 2 * 256];

    const int fg  = blockIdx.x & 63;
    const int nhh = blockIdx.x >> 6;
    const int f2  = fg * 2;
    const int nh0 = nhh * 256;
    const int tid = threadIdx.x;
    const float log_inc = 9.210340371976184f / 255.0f;

    {
        int fi = tid >> 9, d = tid & 511, j = d & 255;
        float arg = (float)(127 - (f2 + fi)) * expf(-(float)j * log_inc);
        sig[fi * 512 + d] = (d < 256) ? sinf(arg) : cosf(arg);
    }
    __syncthreads();

    const int q = tid & 63, ch = tid >> 6;
    const float* p = pk + (size_t)(ch * 32) * 512 + nh0 + 4 * q;
    float4 a0 = make_float4(0.f, 0.f, 0.f, 0.f);
    float4 a1 = make_float4(0.f, 0.f, 0.f, 0.f);
    #pragma unroll
    for (int dd = 0; dd < 32; ++dd) {
        float4 v = __ldg((const float4*)(p + (size_t)dd * 512));
        int d = ch * 32 + dd;
        float s0 = sig[d], s1 = sig[512 + d];
        a0.x = fmaf(s0, v.x, a0.x); a0.y = fmaf(s0, v.y, a0.y);
        a0.z = fmaf(s0, v.z, a0.z); a0.w = fmaf(s0, v.w, a0.w);
        a1.x = fmaf(s1, v.x, a1.x); a1.y = fmaf(s1, v.y, a1.y);
        a1.z = fmaf(s1, v.z, a1.z); a1.w = fmaf(s1, v.w, a1.w);
    }
    *(float4*)&sp[(ch * 2 + 0) * 256 + 4 * q] = a0;
    *(float4*)&sp[(ch * 2 + 1) * 256 + 4 * q] = a1;
    __syncthreads();

    if (tid < 128) {
        int fi = tid >> 6, qq = tid & 63;
        float4 s = make_float4(0.f, 0.f, 0.f, 0.f);
        #pragma unroll
        for (int c = 0; c < 16; ++c) {
            float4 v = *(const float4*)&sp[(c * 2 + fi) * 256 + 4 * qq];
            s.x += v.x; s.y += v.y; s.z += v.z; s.w += v.w;
        }
        const int n  = nhh * 4 + (qq >> 4);
        const int h4 = (4 * qq) & 63;                // multiple of 4
        uint32_t* dst = g_Epk + n * (128 * 32) + (f2 + fi) * 32 + (h4 >> 1);
        dst[0] = pack_h2(s.x, s.y);
        dst[1] = pack_h2(s.z, s.w);
    }
}

// ---------------------------------------------------------------------------
// Main kernel: one CTA per (b,u,n,mh), 256 threads (8 warps, 2m x 4n).
// ---------------------------------------------------------------------------
__global__ __launch_bounds__(256, 3)
void txl_mma_kernel(const float* __restrict__ q_g,
                    const float* __restrict__ k_g,
                    float* __restrict__ out_g) {
    extern __shared__ uint32_t sm[];
    uint32_t smem_base;
    asm("{ .reg .u64 t; cvta.to.shared.u64 t, %1; cvt.u32.u64 %0, t; }"
        : "=r"(smem_base) : "l"(sm));
    const uint32_t sAu = smem_base + OFF_A_B;
    const uint32_t sBu = smem_base + OFF_B_B;
    char* sA_b = reinterpret_cast<char*>(sm) + OFF_A_B;
    char* sB_b = reinterpret_cast<char*>(sm) + OFF_B_B;
    __half* sBD = reinterpret_cast<__half*>(reinterpret_cast<char*>(sm) + OFF_BD_B);

    const int tid = threadIdx.x;
    const int lane = tid & 31, wid = tid >> 5;
    const int wm = wid & 1, wn = wid >> 1;
    const int g = lane >> 2, t = lane & 3;

    const int bid = blockIdx.x;
    const int mh = bid & 1;
    const int n = (bid >> 1) & 7, u = (bid >> 4) & 31, b = bid >> 9;

    const float* Q  = q_g + (size_t)(b * Uu + u) * 128 * 512 + (size_t)mh * 64 * 512 + n * 64;
    const float* Kg = k_g + (size_t)(b * Uu + u) * Cc * 512 + n * 64;
    float* OUT = out_g + (size_t)((b * Nn + n) * Uu + u) * 128 * Cc + (size_t)mh * 64 * Cc;

    // pack-task decode: 32 rows x 8 chunks per pass
    const int t_row0 = tid >> 3;                 // 0..31
    const int t_c    = tid & 7;                  // 16B chunk
    const int t_sc   = t_c ^ (t_row0 & 7);       // swizzled chunk (row offsets are %8==0)
    const int t_hb   = t_c * 8;                  // h base (8 halfs per chunk)
    const uint32_t t_dstoff = (uint32_t)(t_row0 * 128 + t_sc * 16);

    // ---- E -> sB via cp.async with swizzle applied on the fly ----
    {
        const uint32_t* Ep = g_Epk + n * (128 * 32);
        #pragma unroll
        for (int i = 0; i < 4; ++i) {
            int idx = tid + 256 * i;             // 0..1023
            int r = idx >> 3, c = idx & 7;
            int sc = c ^ (r & 7);
            cp16(sBu + (uint32_t)(r * 128 + sc * 16), Ep + r * 32 + c * 4);
        }
        asm volatile("cp.async.commit_group;");
    }

    // ---- pack Q (64 rows) -> sA ----
    #pragma unroll
    for (int it = 0; it < 2; ++it) {
        const int row = t_row0 + 32 * it;
        float4 v0 = *(const float4*)&Q[(size_t)row * 512 + t_hb];
        float4 v1 = *(const float4*)&Q[(size_t)row * 512 + t_hb + 4];
        *(uint4*)(sA_b + t_dstoff + it * 32 * 128) = pack_quad(v0, v1);
    }

    // ---- gather K rows 0..63 (packed) ----
    uint4 krp[2];
    #pragma unroll
    for (int jj = 0; jj < 2; ++jj)
        krp[jj] = gather_pack(Kg, t_row0 + 32 * jj, t_hb, true);

    asm volatile("cp.async.wait_group 0;");
    __syncthreads();

    // ---- BD = Q @ E^T ----
    float accbd[2][4][4] = {};
    gemm_warp(sAu, sBu, accbd, 32 * wm, 32 * wn, lane);
    __syncthreads();                             // E reads complete

    // ---- K0: store rows 0..63; gather rows 64..127; stage BD; store 64..127
    #pragma unroll
    for (int jj = 0; jj < 2; ++jj)
        *(uint4*)(sB_b + t_dstoff + jj * 32 * 128) = krp[jj];
    #pragma unroll
    for (int jj = 0; jj < 2; ++jj)
        krp[jj] = gather_pack(Kg, 64 + t_row0 + 32 * jj, t_hb, true);

    #pragma unroll
    for (int i = 0; i < 2; ++i)
        #pragma unroll
        for (int j = 0; j < 4; ++j) {
            const int w0 = 32 * wm + 16 * i + g;
            const int f0 = 32 * wn + 8 * j + 2 * t;
            sBD[w0 * BDS_H + f0]           = __float2half_rn(accbd[i][j][0]);
            sBD[w0 * BDS_H + f0 + 1]       = __float2half_rn(accbd[i][j][1]);
            sBD[(w0 + 8) * BDS_H + f0]     = __float2half_rn(accbd[i][j][2]);
            sBD[(w0 + 8) * BDS_H + f0 + 1] = __float2half_rn(accbd[i][j][3]);
        }
    #pragma unroll
    for (int jj = 0; jj < 2; ++jj)
        *(uint4*)(sB_b + t_dstoff + (64 + jj * 32) * 128) = krp[jj];
    __syncthreads();

    // ---- AC halves ----
    #pragma unroll 1
    for (int half = 0; half < 2; ++half) {
        float acc[2][4][4] = {};
        gemm_warp(sAu, sBu, acc, 32 * wm, 32 * wn, lane);

        if (half == 0) {
            // gather K1 rows 128..191 while the epilogue runs
            #pragma unroll
            for (int jj = 0; jj < 2; ++jj)
                krp[jj] = gather_pack(Kg, 128 + t_row0 + 32 * jj, t_hb, true);
        }

        // epilogue: add shifted BD (fp16, aligned half2 — index parity proof),
        // direct stores
        #pragma unroll
        for (int i = 0; i < 2; ++i)
            #pragma unroll
            for (int j = 0; j < 4; ++j) {
                const int c0 = 128 * half + 32 * wn + 8 * j + 2 * t;
                #pragma unroll
                for (int p = 0; p < 2; ++p) {
                    const int lw = 32 * wm + 16 * i + g + 8 * p;  // local row
                    const int wg = mh * 64 + lw;                  // global row
                    float v0 = acc[i][j][2 * p];
                    float v1 = acc[i][j][2 * p + 1];
                    const int f = c0 - wg;
                    if (f >= 0 && f < 127) {
                        __half2 h = *reinterpret_cast<const __half2*>(&sBD[lw * BDS_H + f]);
                        float2 bd = __half22float2(h);
                        v0 += bd.x; v1 += bd.y;
                    } else if (f == -1) {
                        v1 += __half2float(sBD[lw * BDS_H]);
                    } else if (f == 127) {
                        v0 += __half2float(sBD[lw * BDS_H + 127]);
                    }
                    float* o = &OUT[(size_t)lw * Cc + c0];
                    o[0] = v0;
                    if (c0 + 1 < Cc) o[1] = v1;
                }
            }

        if (half == 0) {
            __syncthreads();                     // K0 fragment reads complete
            #pragma unroll
            for (int jj = 0; jj < 2; ++jj)
                *(uint4*)(sB_b + t_dstoff + jj * 32 * 128) = krp[jj];
            // gather + store K1 rows 192..255 (row 255 zero)
            #pragma unroll
            for (int jj = 0; jj < 2; ++jj) {
                const int row = 192 + t_row0 + 32 * jj;
                krp[jj] = gather_pack(Kg, row, t_hb, row < Cc);
            }
            #pragma unroll
            for (int jj = 0; jj < 2; ++jj)
                *(uint4*)(sB_b + t_dstoff + (64 + jj * 32) * 128) = krp[jj];
            __syncthreads();
        }
    }
}

// ---------------------------------------------------------------------------
extern "C" void kernel_launch(void* const* d_in, const int* in_sizes, int n_in,
                              void* d_out, int out_size) {
    (void)in_sizes; (void)n_in; (void)out_size;
    const float* q  = (const float*)d_in[0];   // queries (4,32,128,8,64)
    const float* k  = (const float*)d_in[1];   // keys    (4,32,255,8,64)
    const float* pk = (const float*)d_in[2];   // pos_kernel (512,8,64)
    float* out = (float*)d_out;                // (4,8,32,128,255)

    compute_E_kernel<<<128, 1024>>>(pk);

    cudaFuncSetAttribute(txl_mma_kernel,
                         cudaFuncAttributeMaxDynamicSharedMemorySize, SMEM_BYTES);
    txl_mma_kernel<<<2 * 4 * Uu * Nn, 256, SMEM_BYTES>>>(q, k, out);
}